// round 1
// baseline (speedup 1.0000x reference)
#include <cuda_runtime.h>
#include <cstdint>
#include <cstddef>

#define NN 50000
#define NE 800000

// ---------------- scratch (static __device__ arrays; no allocs allowed) ------
__device__ __align__(16) float g_bufA[(size_t)NN * 256];   // 51 MB
__device__ __align__(16) float g_bufB[(size_t)NN * 512];   // 102 MB
__device__ float g_dinv[NN];
__device__ int   g_deg[NN];      // edge counts (no self-loop)
__device__ int   g_off[NN];      // CSR offsets (exclusive scan of g_deg)
__device__ int   g_cur[NN];      // scatter cursors
__device__ int   g_src[NE];      // source node per CSR slot
__device__ float g_gsum[256];    // pooled column sums

// ---------------- setup kernels ---------------------------------------------
__global__ void init_kernel() {
    int i = blockIdx.x * blockDim.x + threadIdx.x;
    if (i < NN) { g_deg[i] = 0; g_cur[i] = 0; }
    if (i < 256) g_gsum[i] = 0.f;
}

__global__ void count_kernel(const int* __restrict__ col, int E) {
    int e = blockIdx.x * blockDim.x + threadIdx.x;
    if (e < E) atomicAdd(&g_deg[col[e]], 1);
}

__global__ void dinv_kernel(int n) {
    int i = blockIdx.x * blockDim.x + threadIdx.x;
    if (i < n) g_dinv[i] = rsqrtf((float)(g_deg[i] + 1));   // +1 = self-loop
}

// single-block exclusive scan over g_deg -> g_off
__global__ void scan_kernel(int n) {
    __shared__ int sm[1024];
    int t = threadIdx.x;
    int carry = 0;
    for (int base = 0; base < n; base += 1024) {
        int i = base + t;
        int v = (i < n) ? g_deg[i] : 0;
        sm[t] = v;
        __syncthreads();
        #pragma unroll
        for (int s = 1; s < 1024; s <<= 1) {
            int add = (t >= s) ? sm[t - s] : 0;
            __syncthreads();
            sm[t] += add;
            __syncthreads();
        }
        if (i < n) g_off[i] = carry + sm[t] - v;   // exclusive
        carry += sm[1023];
        __syncthreads();
    }
}

__global__ void scatter_kernel(const int* __restrict__ row,
                               const int* __restrict__ col, int E) {
    int e = blockIdx.x * blockDim.x + threadIdx.x;
    if (e >= E) return;
    int c = col[e];
    int p = g_off[c] + atomicAdd(&g_cur[c], 1);
    g_src[p] = row[e];
}

// ---------------- propagation: warp-per-node CSR pull ------------------------
// out[n] = dinv[n]^2 * in[n] + sum_{e in CSR[n]} dinv[src]*dinv[n] * in[src]
template <int H>
__global__ void prop_kernel(const float* __restrict__ in,
                            float* __restrict__ out, int n) {
    int warp = (blockIdx.x * blockDim.x + threadIdx.x) >> 5;
    int lane = threadIdx.x & 31;
    if (warp >= n) return;
    constexpr int NV = H / 128;           // float4 per lane
    float dn = g_dinv[warp];
    float ws = dn * dn;
    float4 acc[NV];
    #pragma unroll
    for (int v = 0; v < NV; v++) {
        float4 t = __ldg((const float4*)(in + (size_t)warp * H + v * 128 + lane * 4));
        acc[v].x = t.x * ws; acc[v].y = t.y * ws;
        acc[v].z = t.z * ws; acc[v].w = t.w * ws;
    }
    int s = g_off[warp];
    int e = s + g_deg[warp];
    for (int j = s; j < e; j++) {
        int r = __ldg(&g_src[j]);
        float wr = __ldg(&g_dinv[r]) * dn;
        #pragma unroll
        for (int v = 0; v < NV; v++) {
            float4 t = __ldg((const float4*)(in + (size_t)r * H + v * 128 + lane * 4));
            acc[v].x += t.x * wr; acc[v].y += t.y * wr;
            acc[v].z += t.z * wr; acc[v].w += t.w * wr;
        }
    }
    #pragma unroll
    for (int v = 0; v < NV; v++)
        *(float4*)(out + (size_t)warp * H + v * 128 + lane * 4) = acc[v];
}

// ---------------- fp32 tiled GEMM: C = [relu](A@B + bias) --------------------
// A[M,K] row-major, B[K,N] row-major. BM=128 BN=64 BK=16, 256 thr, 8x4/thread.
__global__ __launch_bounds__(256)
void gemm_kernel(const float* __restrict__ A, const float* __restrict__ B,
                 const float* __restrict__ bias, float* __restrict__ C,
                 int M, int N, int K, int relu) {
    __shared__ float As[16][128];
    __shared__ float Bs[16][64];
    const int tid = threadIdx.x;
    const int m0 = blockIdx.y * 128, n0 = blockIdx.x * 64;
    const int la_m = tid >> 2;          // 0..63
    const int la_k = (tid & 3) << 2;    // 0,4,8,12
    const int lb_k = tid >> 4;          // 0..15
    const int lb_n = (tid & 15) << 2;   // 0..60
    const int tx = tid & 15, ty = tid >> 4;
    float acc[8][4];
    #pragma unroll
    for (int i = 0; i < 8; i++)
        #pragma unroll
        for (int j = 0; j < 4; j++) acc[i][j] = 0.f;

    for (int k0 = 0; k0 < K; k0 += 16) {
        #pragma unroll
        for (int h = 0; h < 2; h++) {
            int m = m0 + la_m + h * 64;
            float4 v = make_float4(0.f, 0.f, 0.f, 0.f);
            if (m < M) v = *(const float4*)(A + (size_t)m * K + k0 + la_k);
            As[la_k + 0][la_m + h * 64] = v.x;
            As[la_k + 1][la_m + h * 64] = v.y;
            As[la_k + 2][la_m + h * 64] = v.z;
            As[la_k + 3][la_m + h * 64] = v.w;
        }
        *(float4*)&Bs[lb_k][lb_n] =
            *(const float4*)(B + (size_t)(k0 + lb_k) * N + n0 + lb_n);
        __syncthreads();
        #pragma unroll
        for (int kk = 0; kk < 16; kk++) {
            float a[8], b[4];
            #pragma unroll
            for (int i = 0; i < 8; i++) a[i] = As[kk][ty * 8 + i];
            #pragma unroll
            for (int j = 0; j < 4; j++) b[j] = Bs[kk][tx * 4 + j];
            #pragma unroll
            for (int i = 0; i < 8; i++)
                #pragma unroll
                for (int j = 0; j < 4; j++) acc[i][j] += a[i] * b[j];
        }
        __syncthreads();
    }
    #pragma unroll
    for (int i = 0; i < 8; i++) {
        int m = m0 + ty * 8 + i;
        if (m >= M) continue;
        #pragma unroll
        for (int j = 0; j < 4; j++) {
            int n = n0 + tx * 4 + j;
            float v = acc[i][j];
            if (bias) v += bias[n];
            if (relu) v = fmaxf(v, 0.f);
            C[(size_t)m * N + n] = v;
        }
    }
}

// ---------------- pool: column sums of relu(in + b3) -------------------------
__global__ void pool_kernel(const float* __restrict__ in,
                            const float* __restrict__ b3, int M) {
    int d = threadIdx.x;                 // 256 threads = 256 dims
    int per = (M + gridDim.x - 1) / gridDim.x;
    int n0 = blockIdx.x * per;
    int n1 = min(M, n0 + per);
    float bias = b3[d];
    float acc = 0.f;
    for (int n = n0; n < n1; n++)
        acc += fmaxf(in[(size_t)n * 256 + d] + bias, 0.f);
    atomicAdd(&g_gsum[d], acc);
}

// ---------------- MLP head (single block) ------------------------------------
__global__ void mlp_kernel(const float* __restrict__ Wf1, const float* __restrict__ bf1,
                           const float* __restrict__ Wf2, const float* __restrict__ bf2,
                           const float* __restrict__ Wf3, const float* __restrict__ bf3,
                           float* __restrict__ out, int M) {
    __shared__ float sg[256], s1[128], s2[64];
    int t = threadIdx.x;
    sg[t] = g_gsum[t] * (1.0f / (float)M);
    __syncthreads();
    if (t < 128) {
        float a = bf1[t];
        for (int k = 0; k < 256; k++) a += sg[k] * Wf1[k * 128 + t];
        s1[t] = fmaxf(a, 0.f);
    }
    __syncthreads();
    if (t < 64) {
        float a = bf2[t];
        for (int k = 0; k < 128; k++) a += s1[k] * Wf2[k * 64 + t];
        s2[t] = fmaxf(a, 0.f);
    }
    __syncthreads();
    if (t == 0) {
        float a = bf3[0];
        for (int k = 0; k < 64; k++) a += s2[k] * Wf3[k];
        out[0] = a;
    }
}

// ---------------- launcher ---------------------------------------------------
extern "C" void kernel_launch(void* const* d_in, const int* in_sizes, int n_in,
                              void* d_out, int out_size) {
    const float* x   = (const float*)d_in[0];
    const int*   ei  = (const int*)  d_in[1];
    const float* W1  = (const float*)d_in[2];  const float* b1  = (const float*)d_in[3];
    const float* W2  = (const float*)d_in[4];  const float* b2  = (const float*)d_in[5];
    const float* W3  = (const float*)d_in[6];  const float* b3  = (const float*)d_in[7];
    const float* Wf1 = (const float*)d_in[8];  const float* bf1 = (const float*)d_in[9];
    const float* Wf2 = (const float*)d_in[10]; const float* bf2 = (const float*)d_in[11];
    const float* Wf3 = (const float*)d_in[12]; const float* bf3 = (const float*)d_in[13];
    float* out = (float*)d_out;

    int M = in_sizes[0] / 128;   // 50000
    int E = in_sizes[1] / 2;     // 800000
    const int* row = ei;
    const int* col = ei + E;

    float *bufA, *bufB;
    cudaGetSymbolAddress((void**)&bufA, g_bufA);
    cudaGetSymbolAddress((void**)&bufB, g_bufB);

    const int T = 256;
    int gN = (NN + T - 1) / T;
    int gE = (E + T - 1) / T;
    int gW = ((size_t)M * 32 + T - 1) / T;   // warp-per-node grids

    // --- graph setup: degrees, dinv, CSR ---
    init_kernel<<<gN, T>>>();
    count_kernel<<<gE, T>>>(col, E);
    dinv_kernel<<<gN, T>>>(M);
    scan_kernel<<<1, 1024>>>(M);
    scatter_kernel<<<gE, T>>>(row, col, E);

    // --- layer 1: p1 = A_hat x ; h1 = relu(p1 @ W1 + b1) ---
    prop_kernel<128><<<gW, T>>>(x, bufA, M);
    {
        dim3 grid(256 / 64, (M + 127) / 128);
        gemm_kernel<<<grid, 256>>>(bufA, W1, b1, bufB, M, 256, 128, 1);
    }
    // --- layer 2: p2 = A_hat h1 ; h2 = relu(p2 @ W2 + b2) ---
    prop_kernel<256><<<gW, T>>>(bufB, bufA, M);
    {
        dim3 grid(512 / 64, (M + 127) / 128);
        gemm_kernel<<<grid, 256>>>(bufA, W2, b2, bufB, M, 512, 256, 1);
    }
    // --- layer 3: t = h2 @ W3 ; p3 = A_hat t ; h3 = relu(p3 + b3) fused w/pool
    {
        dim3 grid(256 / 64, (M + 127) / 128);
        gemm_kernel<<<grid, 256>>>(bufB, W3, nullptr, bufA, M, 256, 512, 0);
    }
    prop_kernel<256><<<gW, T>>>(bufA, bufB, M);

    // --- mean pool + MLP head ---
    pool_kernel<<<200, 256>>>(bufB, b3, M);
    mlp_kernel<<<1, 256>>>(Wf1, bf1, Wf2, bf2, Wf3, bf3, out, M);
}

// round 2
// speedup vs baseline: 1.9860x; 1.9860x over previous
#include <cuda_runtime.h>
#include <cstdint>
#include <cstddef>

#define NN 50000
#define NE 800000

// ---------------- scratch (static __device__ arrays; no allocs allowed) ------
__device__ __align__(16) float g_bufA[(size_t)NN * 256];   // 51 MB
__device__ __align__(16) float g_bufB[(size_t)NN * 512];   // 102 MB
__device__ float g_dinv[NN];
__device__ int   g_deg[NN];      // edge counts (no self-loop)
__device__ int   g_off[NN];      // CSR offsets (exclusive scan of g_deg)
__device__ int   g_cur[NN];      // scatter cursors
__device__ int   g_src[NE];      // source node per CSR slot
__device__ float g_gsum[256];    // pooled column sums

// ---------------- setup kernels ---------------------------------------------
__global__ void init_kernel() {
    int i = blockIdx.x * blockDim.x + threadIdx.x;
    if (i < NN) { g_deg[i] = 0; g_cur[i] = 0; }
    if (i < 256) g_gsum[i] = 0.f;
}

__global__ void count_kernel(const int* __restrict__ col, int E) {
    int e = blockIdx.x * blockDim.x + threadIdx.x;
    if (e < E) atomicAdd(&g_deg[col[e]], 1);
}

__global__ void dinv_kernel(int n) {
    int i = blockIdx.x * blockDim.x + threadIdx.x;
    if (i < n) g_dinv[i] = rsqrtf((float)(g_deg[i] + 1));   // +1 = self-loop
}

// single-block exclusive scan: thread-coarsened + warp shuffle scan
__global__ void scan_kernel(int n) {
    __shared__ int wsum[32];
    int t = threadIdx.x, lane = t & 31, wid = t >> 5;
    const int CH = (n + 1023) >> 10;     // elems per thread
    int start = t * CH;
    int end = min(n, start + CH);
    int s = 0;
    for (int i = start; i < end; i++) s += g_deg[i];
    int v = s;
    #pragma unroll
    for (int d = 1; d < 32; d <<= 1) {
        int u = __shfl_up_sync(0xffffffffu, v, d);
        if (lane >= d) v += u;
    }
    if (lane == 31) wsum[wid] = v;
    __syncthreads();
    if (wid == 0) {
        int w = wsum[lane];
        #pragma unroll
        for (int d = 1; d < 32; d <<= 1) {
            int u = __shfl_up_sync(0xffffffffu, w, d);
            if (lane >= d) w += u;
        }
        wsum[lane] = w;
    }
    __syncthreads();
    int run = (v - s) + (wid ? wsum[wid - 1] : 0);   // exclusive prefix
    for (int i = start; i < end; i++) { g_off[i] = run; run += g_deg[i]; }
}

__global__ void scatter_kernel(const int* __restrict__ row,
                               const int* __restrict__ col, int E) {
    int e = blockIdx.x * blockDim.x + threadIdx.x;
    if (e >= E) return;
    int c = col[e];
    int p = g_off[c] + atomicAdd(&g_cur[c], 1);
    g_src[p] = row[e];
}

// ---------------- propagation: warp-per-node CSR pull ------------------------
template <int H>
__global__ void prop_kernel(const float* __restrict__ in,
                            float* __restrict__ out, int n) {
    int warp = (blockIdx.x * blockDim.x + threadIdx.x) >> 5;
    int lane = threadIdx.x & 31;
    if (warp >= n) return;
    constexpr int NV = H / 128;
    float dn = g_dinv[warp];
    float ws = dn * dn;
    float4 acc[NV];
    #pragma unroll
    for (int v = 0; v < NV; v++) {
        float4 t = __ldg((const float4*)(in + (size_t)warp * H + v * 128 + lane * 4));
        acc[v].x = t.x * ws; acc[v].y = t.y * ws;
        acc[v].z = t.z * ws; acc[v].w = t.w * ws;
    }
    int s = g_off[warp];
    int e = s + g_deg[warp];
    for (int j = s; j < e; j++) {
        int r = __ldg(&g_src[j]);
        float wr = __ldg(&g_dinv[r]) * dn;
        #pragma unroll
        for (int v = 0; v < NV; v++) {
            float4 t = __ldg((const float4*)(in + (size_t)r * H + v * 128 + lane * 4));
            acc[v].x += t.x * wr; acc[v].y += t.y * wr;
            acc[v].z += t.z * wr; acc[v].w += t.w * wr;
        }
    }
    #pragma unroll
    for (int v = 0; v < NV; v++)
        *(float4*)(out + (size_t)warp * H + v * 128 + lane * 4) = acc[v];
}

// ---------------- tf32 tensor-core GEMM: C = [relu](A@B + bias) --------------
// A[M,K] rm, B[K,N] rm. CTA 128x128, 8 warps (warp tile 64x32), BK=32.
// N must be multiple of 128, K multiple of 32 (true: N in {256,512}, K in {128,256,512}).
__device__ __forceinline__ unsigned f2tf(float f) {
    unsigned u; asm("cvt.rna.tf32.f32 %0, %1;" : "=r"(u) : "f"(f)); return u;
}

#define AS_STRIDE 36    // 36 % 32 == 4 -> bank = (4*row + k) % 32, conflict-free
#define BS_STRIDE 132   // 132 % 32 == 4 -> bank = (4*k + n) % 32, conflict-free

__global__ __launch_bounds__(256, 2)
void gemm_tc(const float* __restrict__ A, const float* __restrict__ B,
             const float* __restrict__ bias, float* __restrict__ C,
             int M, int N, int K, int relu) {
    __shared__ unsigned As[128 * AS_STRIDE];
    __shared__ unsigned Bs[32 * BS_STRIDE];
    const int tid = threadIdx.x, lane = tid & 31, wid = tid >> 5;
    const int m0 = blockIdx.y * 128, n0 = blockIdx.x * 128;
    const int wm = (wid >> 2) * 64;   // 0 | 64
    const int wn = (wid & 3) * 32;    // 0..96

    float acc[4][4][4];
    #pragma unroll
    for (int i = 0; i < 4; i++)
        #pragma unroll
        for (int j = 0; j < 4; j++)
            #pragma unroll
            for (int q = 0; q < 4; q++) acc[i][j][q] = 0.f;

    for (int k0 = 0; k0 < K; k0 += 32) {
        // A tile: 128x32 -> 1024 float4, 4 per thread
        #pragma unroll
        for (int i = 0; i < 4; i++) {
            int idx = tid + i * 256;
            int r = idx >> 3, kq = (idx & 7) * 4;
            float4 v = make_float4(0.f, 0.f, 0.f, 0.f);
            if (m0 + r < M)
                v = *(const float4*)(A + (size_t)(m0 + r) * K + k0 + kq);
            unsigned* p = &As[r * AS_STRIDE + kq];
            p[0] = f2tf(v.x); p[1] = f2tf(v.y); p[2] = f2tf(v.z); p[3] = f2tf(v.w);
        }
        // B tile: 32x128 -> 1024 float4, 4 per thread
        #pragma unroll
        for (int i = 0; i < 4; i++) {
            int idx = tid + i * 256;
            int kk = idx >> 5, nq = (idx & 31) * 4;
            float4 v = *(const float4*)(B + (size_t)(k0 + kk) * N + n0 + nq);
            unsigned* p = &Bs[kk * BS_STRIDE + nq];
            p[0] = f2tf(v.x); p[1] = f2tf(v.y); p[2] = f2tf(v.z); p[3] = f2tf(v.w);
        }
        __syncthreads();

        #pragma unroll
        for (int ks = 0; ks < 32; ks += 8) {
            unsigned a[4][4], b[4][2];
            int kc = ks + (lane & 3);
            #pragma unroll
            for (int mt = 0; mt < 4; mt++) {
                int r = wm + mt * 16 + (lane >> 2);
                a[mt][0] = As[r * AS_STRIDE + kc];
                a[mt][1] = As[(r + 8) * AS_STRIDE + kc];
                a[mt][2] = As[r * AS_STRIDE + kc + 4];
                a[mt][3] = As[(r + 8) * AS_STRIDE + kc + 4];
            }
            #pragma unroll
            for (int nt = 0; nt < 4; nt++) {
                int c = wn + nt * 8 + (lane >> 2);
                b[nt][0] = Bs[kc * BS_STRIDE + c];
                b[nt][1] = Bs[(kc + 4) * BS_STRIDE + c];
            }
            #pragma unroll
            for (int mt = 0; mt < 4; mt++)
                #pragma unroll
                for (int nt = 0; nt < 4; nt++)
                    asm volatile(
                        "mma.sync.aligned.m16n8k8.row.col.f32.tf32.tf32.f32 "
                        "{%0,%1,%2,%3}, {%4,%5,%6,%7}, {%8,%9}, {%0,%1,%2,%3};"
                        : "+f"(acc[mt][nt][0]), "+f"(acc[mt][nt][1]),
                          "+f"(acc[mt][nt][2]), "+f"(acc[mt][nt][3])
                        : "r"(a[mt][0]), "r"(a[mt][1]), "r"(a[mt][2]), "r"(a[mt][3]),
                          "r"(b[nt][0]), "r"(b[nt][1]));
        }
        __syncthreads();
    }

    // epilogue: bias + relu, float2 stores (c0/c1 and c2/c3 are col-adjacent)
    #pragma unroll
    for (int mt = 0; mt < 4; mt++) {
        int rbase = m0 + wm + mt * 16 + (lane >> 2);
        #pragma unroll
        for (int nt = 0; nt < 4; nt++) {
            int c = n0 + wn + nt * 8 + (lane & 3) * 2;
            float bx = bias ? bias[c] : 0.f;
            float by = bias ? bias[c + 1] : 0.f;
            #pragma unroll
            for (int h = 0; h < 2; h++) {
                int r = rbase + h * 8;
                if (r >= M) continue;
                float v0 = acc[mt][nt][2 * h] + bx;
                float v1 = acc[mt][nt][2 * h + 1] + by;
                if (relu) { v0 = fmaxf(v0, 0.f); v1 = fmaxf(v1, 0.f); }
                float2 o; o.x = v0; o.y = v1;
                *(float2*)(C + (size_t)r * N + c) = o;
            }
        }
    }
}

// ---------------- pool: column sums of relu(in + b3) -------------------------
__global__ void pool_kernel(const float* __restrict__ in,
                            const float* __restrict__ b3, int M) {
    int d = threadIdx.x;
    int per = (M + gridDim.x - 1) / gridDim.x;
    int n0 = blockIdx.x * per;
    int n1 = min(M, n0 + per);
    float bias = b3[d];
    float acc = 0.f;
    for (int n = n0; n < n1; n++)
        acc += fmaxf(in[(size_t)n * 256 + d] + bias, 0.f);
    atomicAdd(&g_gsum[d], acc);
}

// ---------------- MLP head (single block) ------------------------------------
__global__ void mlp_kernel(const float* __restrict__ Wf1, const float* __restrict__ bf1,
                           const float* __restrict__ Wf2, const float* __restrict__ bf2,
                           const float* __restrict__ Wf3, const float* __restrict__ bf3,
                           float* __restrict__ out, int M) {
    __shared__ float sg[256], s1[128], s2[64];
    int t = threadIdx.x;
    sg[t] = g_gsum[t] * (1.0f / (float)M);
    __syncthreads();
    if (t < 128) {
        float a = bf1[t];
        for (int k = 0; k < 256; k++) a += sg[k] * Wf1[k * 128 + t];
        s1[t] = fmaxf(a, 0.f);
    }
    __syncthreads();
    if (t < 64) {
        float a = bf2[t];
        for (int k = 0; k < 128; k++) a += s1[k] * Wf2[k * 64 + t];
        s2[t] = fmaxf(a, 0.f);
    }
    __syncthreads();
    if (t == 0) {
        float a = bf3[0];
        for (int k = 0; k < 64; k++) a += s2[k] * Wf3[k];
        out[0] = a;
    }
}

// ---------------- launcher ---------------------------------------------------
extern "C" void kernel_launch(void* const* d_in, const int* in_sizes, int n_in,
                              void* d_out, int out_size) {
    const float* x   = (const float*)d_in[0];
    const int*   ei  = (const int*)  d_in[1];
    const float* W1  = (const float*)d_in[2];  const float* b1  = (const float*)d_in[3];
    const float* W2  = (const float*)d_in[4];  const float* b2  = (const float*)d_in[5];
    const float* W3  = (const float*)d_in[6];  const float* b3  = (const float*)d_in[7];
    const float* Wf1 = (const float*)d_in[8];  const float* bf1 = (const float*)d_in[9];
    const float* Wf2 = (const float*)d_in[10]; const float* bf2 = (const float*)d_in[11];
    const float* Wf3 = (const float*)d_in[12]; const float* bf3 = (const float*)d_in[13];
    float* out = (float*)d_out;

    int M = in_sizes[0] / 128;   // 50000
    int E = in_sizes[1] / 2;     // 800000
    const int* row = ei;
    const int* col = ei + E;

    float *bufA, *bufB;
    cudaGetSymbolAddress((void**)&bufA, g_bufA);
    cudaGetSymbolAddress((void**)&bufB, g_bufB);

    const int T = 256;
    int gN = (NN + T - 1) / T;
    int gE = (E + T - 1) / T;
    int gW = ((size_t)M * 32 + T - 1) / T;

    // --- graph setup: degrees, dinv, CSR ---
    init_kernel<<<gN, T>>>();
    count_kernel<<<gE, T>>>(col, E);
    dinv_kernel<<<gN, T>>>(M);
    scan_kernel<<<1, 1024>>>(M);
    scatter_kernel<<<gE, T>>>(row, col, E);

    int gM = (M + 127) / 128;

    // --- layer 1: p1 = A_hat x ; h1 = relu(p1 @ W1 + b1) ---
    prop_kernel<128><<<gW, T>>>(x, bufA, M);
    gemm_tc<<<dim3(256 / 128, gM), 256>>>(bufA, W1, b1, bufB, M, 256, 128, 1);

    // --- layer 2 ---
    prop_kernel<256><<<gW, T>>>(bufB, bufA, M);
    gemm_tc<<<dim3(512 / 128, gM), 256>>>(bufA, W2, b2, bufB, M, 512, 256, 1);

    // --- layer 3: t = h2 @ W3 ; p3 = A_hat t ; relu+bias fused into pool ---
    gemm_tc<<<dim3(256 / 128, gM), 256>>>(bufB, W3, nullptr, bufA, M, 256, 512, 0);
    prop_kernel<256><<<gW, T>>>(bufA, bufB, M);

    // --- mean pool + MLP head ---
    pool_kernel<<<200, 256>>>(bufB, b3, M);
    mlp_kernel<<<1, 256>>>(Wf1, bf1, Wf2, bf2, Wf3, bf3, out, M);
}

// round 4
// speedup vs baseline: 2.5092x; 1.2635x over previous
#include <cuda_runtime.h>
#include <cuda_bf16.h>
#include <cstdint>
#include <cstddef>

#define NN 50000
#define NE 800000
#define SCAN_CH 196          // ceil(50000/256)
#define SCAN_B  256

// ---------------- scratch (static __device__ arrays; no allocs allowed) ------
__device__ __align__(16) __nv_bfloat16 g_bufA[(size_t)NN * 256];  // 25.6 MB
__device__ __align__(16) __nv_bfloat16 g_bufB[(size_t)NN * 512];  // 51.2 MB
__device__ float g_dinv[NN];
__device__ int   g_deg[NN];
__device__ int   g_off[NN];
__device__ int   g_cur[NN];
__device__ int   g_src[NE];
__device__ int   g_bsum[SCAN_B];
__device__ int   g_boff[SCAN_B];
__device__ float g_gsum[256];

// ---------------- setup kernels ---------------------------------------------
__global__ void init_kernel() {
    int i = blockIdx.x * blockDim.x + threadIdx.x;
    if (i < NN) { g_deg[i] = 0; g_cur[i] = 0; }
    if (i < 256) g_gsum[i] = 0.f;
}

__global__ void count_kernel(const int* __restrict__ col, int E) {
    int e = blockIdx.x * blockDim.x + threadIdx.x;
    if (e < E) atomicAdd(&g_deg[col[e]], 1);
}

__global__ void dinv_kernel(int n) {
    int i = blockIdx.x * blockDim.x + threadIdx.x;
    if (i < n) g_dinv[i] = rsqrtf((float)(g_deg[i] + 1));
}

// --- hierarchical exclusive scan of g_deg -> g_off ---------------------------
__global__ void scanA_kernel(int n) {            // per-block partial sums
    __shared__ int ws[8];
    int t = threadIdx.x, lane = t & 31, wid = t >> 5;
    int i = blockIdx.x * SCAN_CH + t;
    int v = (t < SCAN_CH && i < n) ? g_deg[i] : 0;
    #pragma unroll
    for (int d = 16; d > 0; d >>= 1) v += __shfl_down_sync(0xffffffffu, v, d);
    if (lane == 0) ws[wid] = v;
    __syncthreads();
    if (t == 0) {
        int s = 0;
        #pragma unroll
        for (int w = 0; w < 8; w++) s += ws[w];
        g_bsum[blockIdx.x] = s;
    }
}

__global__ void scanB_kernel() {                 // scan 256 block sums
    __shared__ int ws[8];
    int t = threadIdx.x, lane = t & 31, wid = t >> 5;
    int s = g_bsum[t];
    int v = s;
    #pragma unroll
    for (int d = 1; d < 32; d <<= 1) {
        int u = __shfl_up_sync(0xffffffffu, v, d);
        if (lane >= d) v += u;
    }
    if (lane == 31) ws[wid] = v;
    __syncthreads();
    if (wid == 0 && lane < 8) {
        int w = ws[lane];
        #pragma unroll
        for (int d = 1; d < 8; d <<= 1) {
            int u = __shfl_up_sync(0xffu, w, d);
            if (lane >= d) w += u;
        }
        ws[lane] = w;
    }
    __syncthreads();
    g_boff[t] = (v - s) + (wid ? ws[wid - 1] : 0);
}

__global__ void scanC_kernel(int n) {            // local scan + block offset
    __shared__ int ws[8];
    int t = threadIdx.x, lane = t & 31, wid = t >> 5;
    int i = blockIdx.x * SCAN_CH + t;
    int s = (t < SCAN_CH && i < n) ? g_deg[i] : 0;
    int v = s;
    #pragma unroll
    for (int d = 1; d < 32; d <<= 1) {
        int u = __shfl_up_sync(0xffffffffu, v, d);
        if (lane >= d) v += u;
    }
    if (lane == 31) ws[wid] = v;
    __syncthreads();
    if (wid == 0 && lane < 8) {
        int w = ws[lane];
        #pragma unroll
        for (int d = 1; d < 8; d <<= 1) {
            int u = __shfl_up_sync(0xffu, w, d);
            if (lane >= d) w += u;
        }
        ws[lane] = w;
    }
    __syncthreads();
    if (t < SCAN_CH && i < n)
        g_off[i] = g_boff[blockIdx.x] + (v - s) + (wid ? ws[wid - 1] : 0);
}

__global__ void scatter_kernel(const int* __restrict__ row,
                               const int* __restrict__ col, int E) {
    int e = blockIdx.x * blockDim.x + threadIdx.x;
    if (e >= E) return;
    int c = col[e];
    int p = g_off[c] + atomicAdd(&g_cur[c], 1);
    g_src[p] = row[e];
}

// ---------------- propagation kernels ----------------------------------------
// layer 1: fp32 input x (H=128), bf16 output
__global__ void prop_f32_kernel(const float* __restrict__ in,
                                __nv_bfloat16* __restrict__ out, int n) {
    int warp = (blockIdx.x * blockDim.x + threadIdx.x) >> 5;
    int lane = threadIdx.x & 31;
    if (warp >= n) return;
    float dn = g_dinv[warp];
    float ws = dn * dn;
    float4 t = __ldg((const float4*)(in + (size_t)warp * 128 + lane * 4));
    float4 acc = make_float4(t.x * ws, t.y * ws, t.z * ws, t.w * ws);
    int s = g_off[warp];
    int e = s + g_deg[warp];
    for (int j = s; j < e; j++) {
        int r = __ldg(&g_src[j]);
        float wr = __ldg(&g_dinv[r]) * dn;
        float4 u = __ldg((const float4*)(in + (size_t)r * 128 + lane * 4));
        acc.x += u.x * wr; acc.y += u.y * wr; acc.z += u.z * wr; acc.w += u.w * wr;
    }
    __nv_bfloat162 o0 = __floats2bfloat162_rn(acc.x, acc.y);
    __nv_bfloat162 o1 = __floats2bfloat162_rn(acc.z, acc.w);
    uint2 o; o.x = *(unsigned*)&o0; o.y = *(unsigned*)&o1;
    *(uint2*)(out + (size_t)warp * 128 + lane * 4) = o;
}

// bf16 in/out, H=256 (8 bf16 per lane = uint4)
__global__ void prop_bf16_kernel(const __nv_bfloat16* __restrict__ in,
                                 __nv_bfloat16* __restrict__ out, int n) {
    int warp = (blockIdx.x * blockDim.x + threadIdx.x) >> 5;
    int lane = threadIdx.x & 31;
    if (warp >= n) return;
    float dn = g_dinv[warp];
    float ws = dn * dn;
    float acc[8];
    {
        uint4 u = __ldg((const uint4*)(in + (size_t)warp * 256 + lane * 8));
        float2 f0 = __bfloat1622float2(*(__nv_bfloat162*)&u.x);
        float2 f1 = __bfloat1622float2(*(__nv_bfloat162*)&u.y);
        float2 f2 = __bfloat1622float2(*(__nv_bfloat162*)&u.z);
        float2 f3 = __bfloat1622float2(*(__nv_bfloat162*)&u.w);
        acc[0] = f0.x * ws; acc[1] = f0.y * ws; acc[2] = f1.x * ws; acc[3] = f1.y * ws;
        acc[4] = f2.x * ws; acc[5] = f2.y * ws; acc[6] = f3.x * ws; acc[7] = f3.y * ws;
    }
    int s = g_off[warp];
    int e = s + g_deg[warp];
    for (int j = s; j < e; j++) {
        int r = __ldg(&g_src[j]);
        float wr = __ldg(&g_dinv[r]) * dn;
        uint4 u = __ldg((const uint4*)(in + (size_t)r * 256 + lane * 8));
        float2 f0 = __bfloat1622float2(*(__nv_bfloat162*)&u.x);
        float2 f1 = __bfloat1622float2(*(__nv_bfloat162*)&u.y);
        float2 f2 = __bfloat1622float2(*(__nv_bfloat162*)&u.z);
        float2 f3 = __bfloat1622float2(*(__nv_bfloat162*)&u.w);
        acc[0] += f0.x * wr; acc[1] += f0.y * wr; acc[2] += f1.x * wr; acc[3] += f1.y * wr;
        acc[4] += f2.x * wr; acc[5] += f2.y * wr; acc[6] += f3.x * wr; acc[7] += f3.y * wr;
    }
    __nv_bfloat162 o0 = __floats2bfloat162_rn(acc[0], acc[1]);
    __nv_bfloat162 o1 = __floats2bfloat162_rn(acc[2], acc[3]);
    __nv_bfloat162 o2 = __floats2bfloat162_rn(acc[4], acc[5]);
    __nv_bfloat162 o3 = __floats2bfloat162_rn(acc[6], acc[7]);
    uint4 o; o.x = *(unsigned*)&o0; o.y = *(unsigned*)&o1;
    o.z = *(unsigned*)&o2; o.w = *(unsigned*)&o3;
    *(uint4*)(out + (size_t)warp * 256 + lane * 8) = o;
}

// ---------------- tf32 tensor-core GEMM (R2-proven core) ---------------------
// A[M,K] bf16 rm, B[K,N] fp32 rm, C bf16 rm. CTA 128x128, warp tile 64x32, BK=32.
__device__ __forceinline__ unsigned f2tf(float f) {
    unsigned u; asm("cvt.rna.tf32.f32 %0, %1;" : "=r"(u) : "f"(f)); return u;
}
__device__ __forceinline__ unsigned pack_bf2(float a, float b) {
    __nv_bfloat162 h = __floats2bfloat162_rn(a, b);
    return *(unsigned*)&h;
}

#define AS_STRIDE 36
#define BS_STRIDE 132

__global__ __launch_bounds__(256, 2)
void gemm_tc(const __nv_bfloat16* __restrict__ A, const float* __restrict__ B,
             const float* __restrict__ bias, __nv_bfloat16* __restrict__ C,
             int M, int N, int K, int relu) {
    __shared__ unsigned As[128 * AS_STRIDE];
    __shared__ unsigned Bs[32 * BS_STRIDE];
    const int tid = threadIdx.x, lane = tid & 31, wid = tid >> 5;
    const int m0 = blockIdx.y * 128, n0 = blockIdx.x * 128;
    const int wm = (wid >> 2) * 64;
    const int wn = (wid & 3) * 32;

    float acc[4][4][4];
    #pragma unroll
    for (int i = 0; i < 4; i++)
        #pragma unroll
        for (int j = 0; j < 4; j++)
            #pragma unroll
            for (int q = 0; q < 4; q++) acc[i][j][q] = 0.f;

    for (int k0 = 0; k0 < K; k0 += 32) {
        // A tile: 128x32 bf16; 512 8-elem chunks, 2 per thread
        #pragma unroll
        for (int i = 0; i < 2; i++) {
            int idx = tid + i * 256;
            int r = idx >> 2, q = (idx & 3) * 8;
            uint4 v = make_uint4(0u, 0u, 0u, 0u);
            if (m0 + r < M)
                v = *(const uint4*)(A + (size_t)(m0 + r) * K + k0 + q);
            unsigned* p = &As[r * AS_STRIDE + q];
            float2 f;
            f = __bfloat1622float2(*(__nv_bfloat162*)&v.x); p[0] = f2tf(f.x); p[1] = f2tf(f.y);
            f = __bfloat1622float2(*(__nv_bfloat162*)&v.y); p[2] = f2tf(f.x); p[3] = f2tf(f.y);
            f = __bfloat1622float2(*(__nv_bfloat162*)&v.z); p[4] = f2tf(f.x); p[5] = f2tf(f.y);
            f = __bfloat1622float2(*(__nv_bfloat162*)&v.w); p[6] = f2tf(f.x); p[7] = f2tf(f.y);
        }
        // B tile: 32x128 fp32 -> tf32; 1024 float4, 4 per thread  (R2 verbatim)
        #pragma unroll
        for (int i = 0; i < 4; i++) {
            int idx = tid + i * 256;
            int kk = idx >> 5, nq = (idx & 31) * 4;
            float4 v = *(const float4*)(B + (size_t)(k0 + kk) * N + n0 + nq);
            unsigned* p = &Bs[kk * BS_STRIDE + nq];
            p[0] = f2tf(v.x); p[1] = f2tf(v.y); p[2] = f2tf(v.z); p[3] = f2tf(v.w);
        }
        __syncthreads();

        #pragma unroll
        for (int ks = 0; ks < 32; ks += 8) {
            unsigned a[4][4], b[4][2];
            int kc = ks + (lane & 3);
            #pragma unroll
            for (int mt = 0; mt < 4; mt++) {
                int r = wm + mt * 16 + (lane >> 2);
                a[mt][0] = As[r * AS_STRIDE + kc];
                a[mt][1] = As[(r + 8) * AS_STRIDE + kc];
                a[mt][2] = As[r * AS_STRIDE + kc + 4];
                a[mt][3] = As[(r + 8) * AS_STRIDE + kc + 4];
            }
            #pragma unroll
            for (int nt = 0; nt < 4; nt++) {
                int c = wn + nt * 8 + (lane >> 2);
                b[nt][0] = Bs[kc * BS_STRIDE + c];
                b[nt][1] = Bs[(kc + 4) * BS_STRIDE + c];
            }
            #pragma unroll
            for (int mt = 0; mt < 4; mt++)
                #pragma unroll
                for (int nt = 0; nt < 4; nt++)
                    asm volatile(
                        "mma.sync.aligned.m16n8k8.row.col.f32.tf32.tf32.f32 "
                        "{%0,%1,%2,%3}, {%4,%5,%6,%7}, {%8,%9}, {%0,%1,%2,%3};"
                        : "+f"(acc[mt][nt][0]), "+f"(acc[mt][nt][1]),
                          "+f"(acc[mt][nt][2]), "+f"(acc[mt][nt][3])
                        : "r"(a[mt][0]), "r"(a[mt][1]), "r"(a[mt][2]), "r"(a[mt][3]),
                          "r"(b[nt][0]), "r"(b[nt][1]));
        }
        __syncthreads();
    }

    // epilogue: bias + relu, packed bf16 stores
    #pragma unroll
    for (int mt = 0; mt < 4; mt++) {
        int rbase = m0 + wm + mt * 16 + (lane >> 2);
        #pragma unroll
        for (int nt = 0; nt < 4; nt++) {
            int c = n0 + wn + nt * 8 + (lane & 3) * 2;
            float bx = bias ? bias[c] : 0.f;
            float by = bias ? bias[c + 1] : 0.f;
            #pragma unroll
            for (int h = 0; h < 2; h++) {
                int r = rbase + h * 8;
                if (r >= M) continue;
                float v0 = acc[mt][nt][2 * h] + bx;
                float v1 = acc[mt][nt][2 * h + 1] + by;
                if (relu) { v0 = fmaxf(v0, 0.f); v1 = fmaxf(v1, 0.f); }
                *(unsigned*)(C + (size_t)r * N + c) = pack_bf2(v0, v1);
            }
        }
    }
}

// ---------------- pool: column sums of relu(in + b3) -------------------------
__global__ void pool_kernel(const __nv_bfloat16* __restrict__ in,
                            const float* __restrict__ b3, int M) {
    int d = threadIdx.x;
    int per = (M + gridDim.x - 1) / gridDim.x;
    int n0 = blockIdx.x * per;
    int n1 = min(M, n0 + per);
    float bias = b3[d];
    float acc = 0.f;
    for (int n = n0; n < n1; n++)
        acc += fmaxf(__bfloat162float(in[(size_t)n * 256 + d]) + bias, 0.f);
    atomicAdd(&g_gsum[d], acc);
}

// ---------------- MLP head (single block) ------------------------------------
__global__ void mlp_kernel(const float* __restrict__ Wf1, const float* __restrict__ bf1,
                           const float* __restrict__ Wf2, const float* __restrict__ bf2,
                           const float* __restrict__ Wf3, const float* __restrict__ bf3,
                           float* __restrict__ out, int M) {
    __shared__ float sg[256], s1[128], s2[64];
    int t = threadIdx.x;
    sg[t] = g_gsum[t] * (1.0f / (float)M);
    __syncthreads();
    if (t < 128) {
        float a = bf1[t];
        for (int k = 0; k < 256; k++) a += sg[k] * Wf1[k * 128 + t];
        s1[t] = fmaxf(a, 0.f);
    }
    __syncthreads();
    if (t < 64) {
        float a = bf2[t];
        for (int k = 0; k < 128; k++) a += s1[k] * Wf2[k * 64 + t];
        s2[t] = fmaxf(a, 0.f);
    }
    __syncthreads();
    if (t == 0) {
        float a = bf3[0];
        for (int k = 0; k < 64; k++) a += s2[k] * Wf3[k];
        out[0] = a;
    }
}

// ---------------- launcher ---------------------------------------------------
extern "C" void kernel_launch(void* const* d_in, const int* in_sizes, int n_in,
                              void* d_out, int out_size) {
    const float* x   = (const float*)d_in[0];
    const int*   ei  = (const int*)  d_in[1];
    const float* W1  = (const float*)d_in[2];  const float* b1  = (const float*)d_in[3];
    const float* W2  = (const float*)d_in[4];  const float* b2  = (const float*)d_in[5];
    const float* W3  = (const float*)d_in[6];  const float* b3  = (const float*)d_in[7];
    const float* Wf1 = (const float*)d_in[8];  const float* bf1 = (const float*)d_in[9];
    const float* Wf2 = (const float*)d_in[10]; const float* bf2 = (const float*)d_in[11];
    const float* Wf3 = (const float*)d_in[12]; const float* bf3 = (const float*)d_in[13];
    float* out = (float*)d_out;

    int M = in_sizes[0] / 128;   // 50000
    int E = in_sizes[1] / 2;     // 800000
    const int* row = ei;
    const int* col = ei + E;

    __nv_bfloat16 *bufA, *bufB;
    cudaGetSymbolAddress((void**)&bufA, g_bufA);
    cudaGetSymbolAddress((void**)&bufB, g_bufB);

    const int T = 256;
    int gN = (NN + T - 1) / T;
    int gE = (E + T - 1) / T;
    int gW = ((size_t)M * 32 + T - 1) / T;

    // --- graph setup ---
    init_kernel<<<gN, T>>>();
    count_kernel<<<gE, T>>>(col, E);
    dinv_kernel<<<gN, T>>>(M);
    scanA_kernel<<<SCAN_B, 256>>>(M);
    scanB_kernel<<<1, 256>>>();
    scanC_kernel<<<SCAN_B, 256>>>(M);
    scatter_kernel<<<gE, T>>>(row, col, E);

    int gM = (M + 127) / 128;

    // --- layer 1: p1 = A_hat x ; h1 = relu(p1 @ W1 + b1) ---
    prop_f32_kernel<<<gW, T>>>(x, bufA, M);
    gemm_tc<<<dim3(256 / 128, gM), 256>>>(bufA, W1, b1, bufB, M, 256, 128, 1);

    // --- layer 2 ---
    prop_bf16_kernel<<<gW, T>>>(bufB, bufA, M);
    gemm_tc<<<dim3(512 / 128, gM), 256>>>(bufA, W2, b2, bufB, M, 512, 256, 1);

    // --- layer 3: t = h2 @ W3 ; p3 = A_hat t ; relu+bias fused into pool ---
    gemm_tc<<<dim3(256 / 128, gM), 256>>>(bufB, W3, nullptr, bufA, M, 256, 512, 0);
    prop_bf16_kernel<<<gW, T>>>(bufA, bufB, M);

    // --- mean pool + MLP head ---
    pool_kernel<<<200, 256>>>(bufB, b3, M);
    mlp_kernel<<<1, 256>>>(Wf1, bf1, Wf2, bf2, Wf3, bf3, out, M);
}